// round 13
// baseline (speedup 1.0000x reference)
#include <cuda_runtime.h>

#define HD 32
#define SEQ 512
#define BPB 32
#define THREADS 256  // 8 warps = 4 j-groups x 2 b-groups

typedef unsigned long long u64;

__device__ __forceinline__ void ffma2(u64 &d, u64 a, u64 b) {
    asm("fma.rn.f32x2 %0, %1, %2, %0;" : "+l"(d) : "l"(a), "l"(b));
}
__device__ __forceinline__ float2 unpk(u64 v) {
    float2 r; asm("mov.b64 {%0, %1}, %2;" : "=f"(r.x), "=f"(r.y) : "l"(v)); return r;
}
__device__ __forceinline__ float tanha(float x) {
    float y; asm("tanh.approx.f32 %0, %1;" : "=f"(y) : "f"(x)); return y;
}
__device__ __forceinline__ float sigm(float x) {
    return fmaf(tanha(0.5f * x), 0.5f, 0.5f);
}

// smem layout (floats)
#define W_STRIDE 36                       // j step = 36 words -> banks 4j..4j+3 (conflict-free, 1 wf deduped)
#define W_MAT    (128 * W_STRIDE)         // 4608
#define X_STRIDE 33
#define H_STRIDE 36                       // batch step 36 words -> sublane banks {0,4,8,12} (conflict-free)
#define OFF_X  (3 * W_MAT)                              // 13824
#define OFF_H1 (OFF_X + SEQ * X_STRIDE)                 // 30720 : h1[2][32][36]
#define OFF_H2 (OFF_H1 + 2 * BPB * H_STRIDE)            // 33024 : h2[2][32][36]
#define SMEM_FLOATS (OFF_H2 + 2 * BPB * H_STRIDE)       // 35328 floats = 141312 B

// 32xK matvec for 4 batches (rows b_base+sub, +4, +8, +12), K packed in pairs.
// wbase: lane row j of matrix (gate stride 32*W_STRIDE). hbase: h[b_base+sub] row.
__device__ __forceinline__ void matvec4(u64 (&acc)[4][4],
                                        const char* wbase,
                                        const char* hbase) {
#pragma unroll
    for (int c = 0; c < 8; ++c) {
        ulonglong2 wv[4];
#pragma unroll
        for (int g = 0; g < 4; ++g)
            wv[g] = *(const ulonglong2*)(wbase + g * (32 * W_STRIDE * 4) + c * 16);
#pragma unroll
        for (int bb = 0; bb < 4; ++bb) {
            ulonglong2 hv = *(const ulonglong2*)(hbase + bb * (4 * H_STRIDE * 4) + c * 16);
#pragma unroll
            for (int g = 0; g < 4; ++g) {
                ffma2(acc[g][bb], wv[g].x, hv.x);
                ffma2(acc[g][bb], wv[g].y, hv.y);
            }
        }
    }
}

extern "C" __global__ void __launch_bounds__(THREADS, 1)
lstm_kernel(const float* __restrict__ x,
            const float* __restrict__ w_ih0, const float* __restrict__ w_hh0,
            const float* __restrict__ b_ih0, const float* __restrict__ b_hh0,
            const float* __restrict__ w_ih1, const float* __restrict__ w_hh1,
            const float* __restrict__ b_ih1, const float* __restrict__ b_hh1,
            const float* __restrict__ fc1_w, const float* __restrict__ fc1_b,
            const float* __restrict__ fc2_w, const float* __restrict__ fc2_b,
            float* __restrict__ out) {
    extern __shared__ float sm[];
    float* wsm = sm;
    float* xs  = sm + OFF_X;
    float* h1buf[2] = { sm + OFF_H1, sm + OFF_H1 + BPB * H_STRIDE };
    float* h2buf[2] = { sm + OFF_H2, sm + OFF_H2 + BPB * H_STRIDE };

    const int tid  = threadIdx.x;
    const int bblk = blockIdx.x * BPB;

    // ---- weights into padded smem ----
    for (int i = tid; i < 3 * 128 * 32; i += THREADS) {
        int m = i >> 12;
        int r = (i >> 5) & 127;
        int k = i & 31;
        const float* src = (m == 0) ? w_hh0 : (m == 1) ? w_ih1 : w_hh1;
        wsm[m * W_MAT + r * W_STRIDE + k] = src[r * 32 + k];
    }
    // ---- x tile transposed [s][b] ----
    for (int i = tid; i < BPB * SEQ; i += THREADS) {
        int b = i >> 9;
        int s = i & (SEQ - 1);
        xs[s * X_STRIDE + b] = x[(size_t)(bblk + b) * SEQ + s];
    }
    for (int i = tid; i < BPB * H_STRIDE; i += THREADS) {
        h1buf[0][i] = 0.0f; h1buf[1][i] = 0.0f;
        h2buf[0][i] = 0.0f; h2buf[1][i] = 0.0f;
    }
    __syncthreads();

    const int wid    = tid >> 5;
    const int lane   = tid & 31;
    const int j_loc  = lane & 7;
    const int sub    = lane >> 3;
    const int jg     = wid & 3;
    const int bg     = wid >> 2;
    const int j      = jg * 8 + j_loc;
    const int b_base = bg * 16;          // lane's batches: b_base + bb*4 + sub

    const char* w0base = (const char*)(wsm)             + (size_t)j * (W_STRIDE * 4);
    const char* w1base = (const char*)(wsm + W_MAT)     + (size_t)j * (W_STRIDE * 4);
    const char* w2base = (const char*)(wsm + 2 * W_MAT) + (size_t)j * (W_STRIDE * 4);

    float wx[4], bi0[4], bi1[4];
#pragma unroll
    for (int g = 0; g < 4; ++g) {
        int r = g * 32 + j;
        wx[g]  = w_ih0[r];
        bi0[g] = b_ih0[r] + b_hh0[r];
        bi1[g] = b_ih1[r] + b_hh1[r];
    }

    // per-lane h row pointers (batch b_base+sub) for both buffers
    const char* h1p[2] = {
        (const char*)(h1buf[0] + (b_base + sub) * H_STRIDE),
        (const char*)(h1buf[1] + (b_base + sub) * H_STRIDE) };
    const char* h2p[2] = {
        (const char*)(h2buf[0] + (b_base + sub) * H_STRIDE),
        (const char*)(h2buf[1] + (b_base + sub) * H_STRIDE) };

    float c1[4], c2[4];
#pragma unroll
    for (int b = 0; b < 4; ++b) { c1[b] = 0.0f; c2[b] = 0.0f; }

#pragma unroll 1
    for (int s = 0; s < SEQ; ++s) {
        const int rd = (s + 1) & 1;
        const int wr = s & 1;

        // ---- A: L1 recurrent matvec (reads h1[rd]) ----
        u64 acc[4][4];
#pragma unroll
        for (int g = 0; g < 4; ++g)
#pragma unroll
            for (int b = 0; b < 4; ++b) acc[g][b] = 0ull;
        matvec4(acc, w0base, h1p[rd]);

        // ---- B: L1 cells + store h1[wr] ----
#pragma unroll
        for (int bb = 0; bb < 4; ++bb) {
            int b = b_base + bb * 4 + sub;
            float xv = xs[s * X_STRIDE + b];
            float2 t;
            t = unpk(acc[0][bb]); float gi = sigm (t.x + t.y + fmaf(xv, wx[0], bi0[0]));
            t = unpk(acc[1][bb]); float gf = sigm (t.x + t.y + fmaf(xv, wx[1], bi0[1]));
            t = unpk(acc[2][bb]); float gg = tanha(t.x + t.y + fmaf(xv, wx[2], bi0[2]));
            t = unpk(acc[3][bb]); float go = sigm (t.x + t.y + fmaf(xv, wx[3], bi0[3]));
            float cn = fmaf(gf, c1[bb], gi * gg);
            c1[bb] = cn;
            h1buf[wr][b * H_STRIDE + j] = go * tanha(cn);
        }
        __syncthreads();                 // h1[wr] complete (all 32 j from 4 j-group warps)

        // ---- C: L2 matvecs (h1[wr] fresh + h2[rd]) + cells + store h2[wr] ----
#pragma unroll
        for (int g = 0; g < 4; ++g)
#pragma unroll
            for (int b = 0; b < 4; ++b) acc[g][b] = 0ull;
        matvec4(acc, w1base, h1p[wr]);
        matvec4(acc, w2base, h2p[rd]);

#pragma unroll
        for (int bb = 0; bb < 4; ++bb) {
            int b = b_base + bb * 4 + sub;
            float2 t;
            t = unpk(acc[0][bb]); float gi = sigm (t.x + t.y + bi1[0]);
            t = unpk(acc[1][bb]); float gf = sigm (t.x + t.y + bi1[1]);
            t = unpk(acc[2][bb]); float gg = tanha(t.x + t.y + bi1[2]);
            t = unpk(acc[3][bb]); float go = sigm (t.x + t.y + bi1[3]);
            float cn = fmaf(gf, c2[bb], gi * gg);
            c2[bb] = cn;
            h2buf[wr][b * H_STRIDE + j] = go * tanha(cn);
        }
        __syncthreads();                 // h2[wr] complete; prev-state reads all done
    }

    // ================= FC head =================
    if (tid < BPB) {
        const float* h = h2buf[(SEQ - 1) & 1] + tid * H_STRIDE;
        float a1[16];
#pragma unroll
        for (int l = 0; l < 16; ++l) a1[l] = fc1_b[l];
#pragma unroll
        for (int k = 0; k < HD; ++k) {
            float hv = h[k];
#pragma unroll
            for (int l = 0; l < 16; ++l)
                a1[l] = fmaf(fc1_w[l * HD + k], hv, a1[l]);
        }
        float y = fc2_b[0];
#pragma unroll
        for (int l = 0; l < 16; ++l) {
            float a = a1[l];
            a = (a >= 0.0f) ? a : 0.2f * a;
            y = fmaf(fc2_w[l], a, y);
        }
        out[bblk + tid] = y;
    }
}

extern "C" void kernel_launch(void* const* d_in, const int* in_sizes, int n_in,
                              void* d_out, int out_size) {
    const float* x     = (const float*)d_in[0];
    const float* w_ih0 = (const float*)d_in[1];
    const float* w_hh0 = (const float*)d_in[2];
    const float* b_ih0 = (const float*)d_in[3];
    const float* b_hh0 = (const float*)d_in[4];
    const float* w_ih1 = (const float*)d_in[5];
    const float* w_hh1 = (const float*)d_in[6];
    const float* b_ih1 = (const float*)d_in[7];
    const float* b_hh1 = (const float*)d_in[8];
    const float* fc1_w = (const float*)d_in[9];
    const float* fc1_b = (const float*)d_in[10];
    const float* fc2_w = (const float*)d_in[11];
    const float* fc2_b = (const float*)d_in[12];
    float* out = (float*)d_out;

    int B = in_sizes[0] / SEQ;          // 4096
    int grid = B / BPB;                 // 128
    size_t smem = SMEM_FLOATS * sizeof(float);

    cudaFuncSetAttribute(lstm_kernel, cudaFuncAttributeMaxDynamicSharedMemorySize, (int)smem);
    lstm_kernel<<<grid, THREADS, smem>>>(x, w_ih0, w_hh0, b_ih0, b_hh0,
                                         w_ih1, w_hh1, b_ih1, b_hh1,
                                         fc1_w, fc1_b, fc2_w, fc2_b, out);
}